// round 4
// baseline (speedup 1.0000x reference)
#include <cuda_runtime.h>
#include <cstdint>

#define NFINE   1000000
#define FE      9
#define KDIM    288
#define NF      64
#define BLOCK_M 256
#define THREADS 512              // 16 warps: (wid&7)=m-tile(m32), (wid>>3)=n-half(n32)
#define WSTRIDE 72               // B row stride (floats): bank=(8*qc+qr)%32, bijective
#define ASTRIDE 36               // A row stride (floats): bank=(4*qr+qc)%32, bijective

// smem layout (u32 units)
#define WS_U32   (KDIM * WSTRIDE)          // 20736
#define A_OFF    WS_U32
#define A_U32    (BLOCK_M * ASTRIDE)       // 9216 per slab buffer
#define IDX_OFF  (A_OFF + 2 * A_U32)       // 39168
#define IDX_U32  (BLOCK_M * FE)            // 2304 per idx buffer
#define SMEM_U32 (IDX_OFF + 2 * IDX_U32)   // 43776
#define SMEM_BYTES (SMEM_U32 * 4)          // 175104 -> 1 CTA/SM, 16 warps

__device__ __forceinline__ void cp_commit() { asm volatile("cp.async.commit_group;"); }
template<int N> __device__ __forceinline__ void cp_wait() {
    asm volatile("cp.async.wait_group %0;" :: "n"(N));
}

// Gather one neighbor slab j: 256 rows x 128B, 4 cp.async(16B) per thread.
__device__ __forceinline__ void gather_slab(const float* __restrict__ coarse,
                                            const int* __restrict__ sidx, int j,
                                            uint32_t abuf)
{
    #pragma unroll
    for (int i = 0; i < 4; ++i) {
        int o   = i * THREADS + threadIdx.x;
        int r   = o >> 3;
        int seg = o & 7;
        int idx = sidx[r * FE + j];
        const char* src = (const char*)coarse + ((size_t)(unsigned)idx << 7) + (seg << 4);
        uint32_t dst = abuf + (uint32_t)r * (ASTRIDE * 4) + (uint32_t)(seg << 4);
        asm volatile("cp.async.cg.shared.global [%0], [%1], 16;" :: "r"(dst), "l"(src));
    }
}

// Stage 256x9 neighbor indices for one tile.
__device__ __forceinline__ void stage_idx(const int* __restrict__ nbr, int tile,
                                          uint32_t dst)
{
    const size_t base = (size_t)tile * (BLOCK_M * FE);
    if (base + BLOCK_M * FE <= (size_t)NFINE * FE) {
        #pragma unroll
        for (int c = threadIdx.x; c < BLOCK_M * FE / 4; c += THREADS)
            asm volatile("cp.async.ca.shared.global [%0], [%1], 16;"
                         :: "r"(dst + c * 16), "l"(nbr + base + c * 4));
    } else {
        const size_t gmax = (size_t)NFINE * FE - 1;
        for (int i = threadIdx.x; i < BLOCK_M * FE; i += THREADS) {
            size_t g = base + i; if (g > gmax) g = gmax;
            asm volatile("cp.async.ca.shared.global [%0], [%1], 4;"
                         :: "r"(dst + i * 4), "l"(nbr + g));
        }
    }
}

__global__ void __launch_bounds__(THREADS, 1)
finefy_tf32_kernel(const float* __restrict__ coarse,
                   const int*   __restrict__ nbr,
                   const float* __restrict__ weight,
                   float*       __restrict__ out,
                   int numTiles)
{
    extern __shared__ uint32_t sm_[];
    uint32_t* ws = sm_;
    const uint32_t sb = (uint32_t)__cvta_generic_to_shared(sm_);

    const int tid  = threadIdx.x;
    const int lane = tid & 31;
    const int wid  = tid >> 5;
    const int qr   = lane >> 2;      // 0..7
    const int qc   = lane & 3;       // 0..3
    const int mw   = wid & 7;        // m-tile (rows mw*32 .. +31)
    const int nh   = wid >> 3;       // n-half (cols nh*32 .. +31)

    // Weight -> tf32 into padded smem, once.
    for (int i = tid; i < KDIM * NF; i += THREADS) {
        int k = i >> 6, n = i & 63;
        uint32_t t;
        asm("cvt.rna.tf32.f32 %0, %1;" : "=r"(t) : "f"(weight[i]));
        ws[k * WSTRIDE + n] = t;
    }

    const int step = gridDim.x;
    int tile = blockIdx.x;
    int ibuf = 0;   // idx buffer holding current tile's indices
    int sbuf = 0;   // slab buffer holding the slab about to be computed

    if (tile < numTiles) {
        stage_idx(nbr, tile, sb + IDX_OFF * 4);
        cp_commit(); cp_wait<0>(); __syncthreads();
        gather_slab(coarse, (const int*)(sm_ + IDX_OFF), 0, sb + A_OFF * 4);
        cp_commit();
    }

    for (; tile < numTiles; tile += step) {
        const int* sidx = (const int*)(sm_ + IDX_OFF + ibuf * IDX_U32);

        float acc[8][4];
        #pragma unroll
        for (int i = 0; i < 8; ++i) {
            acc[i][0] = 0.f; acc[i][1] = 0.f; acc[i][2] = 0.f; acc[i][3] = 0.f;
        }

        for (int j = 0; j < FE; ++j) {
            if (j < FE - 1) {
                gather_slab(coarse, sidx, j + 1, sb + (A_OFF + (sbuf ^ 1) * A_U32) * 4);
                if (j == FE - 2 && tile + step < numTiles)
                    stage_idx(nbr, tile + step, sb + (IDX_OFF + (ibuf ^ 1) * IDX_U32) * 4);
                cp_commit();
                cp_wait<1>();            // slab j landed; slab j+1 in flight
            } else {
                cp_wait<0>();            // last slab (+ next idx) landed
            }
            __syncthreads();             // slab j visible to all warps

            const uint32_t* ar = sm_ + A_OFF + sbuf * A_U32 + (mw * 32 + qr) * ASTRIDE + qc;

            #pragma unroll
            for (int kk = 0; kk < 4; ++kk) {
                const int c = kk * 8;
                uint32_t a0 = ar[c];
                uint32_t a2 = ar[c + 4];
                uint32_t a1 = ar[c + 8  * ASTRIDE];
                uint32_t a3 = ar[c + 8  * ASTRIDE + 4];
                uint32_t a4 = ar[c + 16 * ASTRIDE];
                uint32_t a6 = ar[c + 16 * ASTRIDE + 4];
                uint32_t a5 = ar[c + 24 * ASTRIDE];
                uint32_t a7 = ar[c + 24 * ASTRIDE + 4];

                const uint32_t* wrow = ws + (j * 32 + kk * 8 + qc) * WSTRIDE + nh * 32 + qr;

                #pragma unroll
                for (int t = 0; t < 4; ++t) {
                    uint32_t b0 = wrow[t * 8];
                    uint32_t b1 = wrow[t * 8 + 4 * WSTRIDE];
                    asm volatile(
                        "mma.sync.aligned.m16n8k8.row.col.f32.tf32.tf32.f32 "
                        "{%0,%1,%2,%3}, {%4,%5,%6,%7}, {%8,%9}, {%0,%1,%2,%3};"
                        : "+f"(acc[2*t][0]), "+f"(acc[2*t][1]),
                          "+f"(acc[2*t][2]), "+f"(acc[2*t][3])
                        : "r"(a0), "r"(a1), "r"(a2), "r"(a3), "r"(b0), "r"(b1));
                    asm volatile(
                        "mma.sync.aligned.m16n8k8.row.col.f32.tf32.tf32.f32 "
                        "{%0,%1,%2,%3}, {%4,%5,%6,%7}, {%8,%9}, {%0,%1,%2,%3};"
                        : "+f"(acc[2*t+1][0]), "+f"(acc[2*t+1][1]),
                          "+f"(acc[2*t+1][2]), "+f"(acc[2*t+1][3])
                        : "r"(a4), "r"(a5), "r"(a6), "r"(a7), "r"(b0), "r"(b1));
                }
            }
            __syncthreads();             // all warps done with slab j before overwrite
            sbuf ^= 1;
        }

        // Prefetch next tile's slab 0 so its L2 latency hides under the epilogue.
        if (tile + step < numTiles) {
            gather_slab(coarse, (const int*)(sm_ + IDX_OFF + (ibuf ^ 1) * IDX_U32), 0,
                        sb + (A_OFF + sbuf * A_U32) * 4);
            cp_commit();
        }

        // Epilogue: coalesced streaming float2 stores.
        const int rowbase = tile * BLOCK_M;
        #pragma unroll
        for (int s = 0; s < 2; ++s) {
            #pragma unroll
            for (int h = 0; h < 2; ++h) {
                int r = rowbase + mw * 32 + s * 16 + h * 8 + qr;
                if (r < NFINE) {
                    float2* po = (float2*)(out + (size_t)r * NF + nh * 32 + qc * 2);
                    #pragma unroll
                    for (int t = 0; t < 4; ++t)
                        __stcs(po + t * 4,
                               make_float2(acc[2*t + s][2*h], acc[2*t + s][2*h + 1]));
                }
            }
        }
        ibuf ^= 1;
    }
}

extern "C" void kernel_launch(void* const* d_in, const int* in_sizes, int n_in,
                              void* d_out, int out_size)
{
    const float* coarse = (const float*)d_in[0];   // [250000, 32] f32
    const int*   nbr    = (const int*)  d_in[1];   // [1000000, 9] i32
    const float* weight = (const float*)d_in[2];   // [288, 64] f32
    float*       out    = (float*)d_out;           // [1000000, 64] f32

    cudaFuncSetAttribute(finefy_tf32_kernel,
                         cudaFuncAttributeMaxDynamicSharedMemorySize, SMEM_BYTES);

    int nsm = 148;
    cudaDeviceGetAttribute(&nsm, cudaDevAttrMultiProcessorCount, 0);

    const int numTiles = (NFINE + BLOCK_M - 1) / BLOCK_M;   // 3907
    finefy_tf32_kernel<<<nsm, THREADS, SMEM_BYTES>>>(coarse, nbr, weight, out, numTiles);
}